// round 5
// baseline (speedup 1.0000x reference)
#include <cuda_runtime.h>
#include <cuda_bf16.h>
#include <cstdint>

#define Bn   2048
#define Nin  512
#define Tn   100
#define H1n  512
#define H2n  256
#define On   5
#define Mn   (Tn*Bn)   // 204800 rows = (t,b)

// ---------------- scratch (device globals: allocation-free) ----------------
__device__ __nv_bfloat16 g_xh[(size_t)Mn * Nin];
__device__ __nv_bfloat16 g_xm[(size_t)Mn * Nin];
__device__ __nv_bfloat16 g_xl[(size_t)Mn * Nin];
__device__ float         g_h1[(size_t)Mn * H1n];
__device__ __nv_bfloat16 g_s1[(size_t)Mn * H1n];
__device__ float         g_h2[(size_t)Mn * H2n];
__device__ __nv_bfloat16 g_s2[(size_t)Mn * H2n];
__device__ __nv_bfloat16 g_W1h[H1n * Nin], g_W1m[H1n * Nin], g_W1l[H1n * Nin];
__device__ __nv_bfloat16 g_W2h[H2n * H1n], g_W2m[H2n * H1n], g_W2l[H2n * H1n];

// ---------------- PTX helpers ----------------------------------------------
__device__ __forceinline__ uint32_t smem_u32(const void* p) {
    uint32_t a;
    asm("{ .reg .u64 t; cvta.to.shared.u64 t, %1; cvt.u32.u64 %0, t; }" : "=r"(a) : "l"(p));
    return a;
}
__device__ __forceinline__ void cp16(uint32_t dst, const void* src) {
    asm volatile("cp.async.cg.shared.global [%0], [%1], 16;" :: "r"(dst), "l"(src));
}
__device__ __forceinline__ void ldsm_x4(uint32_t& r0, uint32_t& r1, uint32_t& r2,
                                        uint32_t& r3, uint32_t addr) {
    asm volatile("ldmatrix.sync.aligned.m8n8.x4.shared.b16 {%0,%1,%2,%3}, [%4];"
                 : "=r"(r0), "=r"(r1), "=r"(r2), "=r"(r3) : "r"(addr));
}
__device__ __forceinline__ void mma16816(float& d0, float& d1, float& d2, float& d3,
                                         uint32_t a0, uint32_t a1, uint32_t a2, uint32_t a3,
                                         uint32_t b0, uint32_t b1) {
    asm volatile("mma.sync.aligned.m16n8k16.row.col.f32.bf16.bf16.f32 "
                 "{%0,%1,%2,%3}, {%4,%5,%6,%7}, {%8,%9}, {%0,%1,%2,%3};"
                 : "+f"(d0), "+f"(d1), "+f"(d2), "+f"(d3)
                 : "r"(a0), "r"(a1), "r"(a2), "r"(a3), "r"(b0), "r"(b1));
}

// ---------------- weight split: fp32 -> bf16 h/m/l --------------------------
template <int MODE>
__global__ void k_wsplit(const float* __restrict__ src, int n) {
    int i = blockIdx.x * blockDim.x + threadIdx.x;
    if (i >= n) return;
    float v = src[i];
    __nv_bfloat16 h = __float2bfloat16(v);
    float r1 = v - __bfloat162float(h);
    __nv_bfloat16 m = __float2bfloat16(r1);
    __nv_bfloat16 l = __float2bfloat16(r1 - __bfloat162float(m));
    if (MODE == 1) { g_W1h[i] = h; g_W1m[i] = m; g_W1l[i] = l; }
    else           { g_W2h[i] = h; g_W2m[i] = m; g_W2l[i] = l; }
}

// ---------------- transpose + 3-split x (B,N,T) -> x{h,m,l}[(t*B+b)*N + n] --
__global__ void k_transpose(const float* __restrict__ x) {
    __shared__ float tile[32][33];
    int b  = blockIdx.x;
    int n0 = blockIdx.y * 32;
    int t0 = blockIdx.z * 32;
    int tx = threadIdx.x, ty = threadIdx.y;   // 32 x 8
#pragma unroll
    for (int i = 0; i < 4; i++) {
        int n = n0 + ty + i * 8, t = t0 + tx;
        if (t < Tn) tile[ty + i * 8][tx] = x[((size_t)b * Nin + n) * Tn + t];
    }
    __syncthreads();
#pragma unroll
    for (int i = 0; i < 4; i++) {
        int t = t0 + ty + i * 8, n = n0 + tx;
        if (t < Tn) {
            float v = tile[tx][ty + i * 8];
            __nv_bfloat16 h = __float2bfloat16(v);
            float r1 = v - __bfloat162float(h);
            __nv_bfloat16 m = __float2bfloat16(r1);
            __nv_bfloat16 l = __float2bfloat16(r1 - __bfloat162float(m));
            size_t idx = ((size_t)t * Bn + b) * Nin + n;
            g_xh[idx] = h; g_xm[idx] = m; g_xl[idx] = l;
        }
    }
}

// ---------------- HMMA bf16 multi-pass GEMM ---------------------------------
// C[m][n] = sum_pass sum_k Ap[m][k] * Bp[n][k]  + bias[n]
// CTA tile 128x128, BK=32, 8 warps (4M x 2N), warp tile 32x64,
// mma.sync m16n8k16, cp.async double buffer, padded smem (stride 40 bf16).
#define SROW 40   // bf16 elems per smem row (80B: 16B-aligned, conflict-free)

template <int NT, int NPASS, int MODE>
__global__ __launch_bounds__(256) void k_gemm(const float* __restrict__ bias,
                                              float* __restrict__ C) {
    __shared__ __align__(16) __nv_bfloat16 sA[2][128 * SROW];
    __shared__ __align__(16) __nv_bfloat16 sB[2][128 * SROW];

    const int tid = threadIdx.x;
    const int wid = tid >> 5;
    const int lane = tid & 31;
    const int wm = wid >> 1;        // 0..3 -> m offset wm*32
    const int wn = wid & 1;         // 0..1 -> n offset wn*64
    const size_t m0 = (size_t)blockIdx.y * 128;
    const int n0 = blockIdx.x * 128;

    const int lrow = tid >> 2;      // 0..63 (load row base, x2)
    const int lch  = tid & 3;       // 16B chunk

    float d[2][8][4];
#pragma unroll
    for (int i = 0; i < 2; i++)
#pragma unroll
        for (int j = 0; j < 8; j++)
#pragma unroll
            for (int k = 0; k < 4; k++) d[i][j][k] = 0.0f;

    const uint32_t sAb = smem_u32(&sA[0][0]);
    const uint32_t sBb = smem_u32(&sB[0][0]);
    const uint32_t bufstride = 128 * SROW * 2;   // bytes per buffer

    auto do_loads = [&](int kc, int buf) {
        int pass = kc >> 4;
        int kb = (kc & 15) * 32;
        const __nv_bfloat16 *Ap, *Bp;
        if (MODE == 1) {
            switch (pass) {
                case 0: Ap = g_xh; Bp = g_W1h; break;
                case 1: Ap = g_xh; Bp = g_W1m; break;
                case 2: Ap = g_xm; Bp = g_W1h; break;
                case 3: Ap = g_xh; Bp = g_W1l; break;
                case 4: Ap = g_xm; Bp = g_W1m; break;
                default: Ap = g_xl; Bp = g_W1h; break;
            }
        } else {
            Ap = g_s1;
            Bp = (pass == 0) ? g_W2h : (pass == 1) ? g_W2m : g_W2l;
        }
        uint32_t aB = sAb + buf * bufstride;
        uint32_t bB = sBb + buf * bufstride;
#pragma unroll
        for (int i = 0; i < 2; i++) {
            int row = lrow + 64 * i;
            cp16(aB + (row * SROW + lch * 8) * 2, Ap + (m0 + row) * 512 + kb + lch * 8);
            cp16(bB + (row * SROW + lch * 8) * 2, Bp + (size_t)(n0 + row) * 512 + kb + lch * 8);
        }
        asm volatile("cp.async.commit_group;");
    };

    constexpr int KC = NPASS * 16;
    do_loads(0, 0);
    for (int kc = 0; kc < KC; kc++) {
        const int buf = kc & 1;
        if (kc + 1 < KC) {
            do_loads(kc + 1, buf ^ 1);
            asm volatile("cp.async.wait_group 1;");
        } else {
            asm volatile("cp.async.wait_group 0;");
        }
        __syncthreads();

        const uint32_t aB = sAb + buf * bufstride;
        const uint32_t bB = sBb + buf * bufstride;
#pragma unroll
        for (int ks = 0; ks < 2; ks++) {
            // A frags: 2 m16 tiles
            uint32_t a[2][4];
#pragma unroll
            for (int mt = 0; mt < 2; mt++) {
                int row = wm * 32 + mt * 16 + (lane & 15);
                uint32_t addr = aB + (row * SROW + ks * 16) * 2 + (lane >> 4) * 16;
                ldsm_x4(a[mt][0], a[mt][1], a[mt][2], a[mt][3], addr);
            }
            // B frags: 8 n8 tiles, loaded as 4 x4-ldmatrix (2 tiles each)
            uint32_t b[4][4];
#pragma unroll
            for (int p = 0; p < 4; p++) {
                int g = lane >> 3;   // 0..3: (tile 2p + g/2, k-half g&1)
                int row = wn * 64 + (2 * p + (g >> 1)) * 8 + (lane & 7);
                uint32_t addr = bB + (row * SROW + ks * 16) * 2 + (g & 1) * 16;
                ldsm_x4(b[p][0], b[p][1], b[p][2], b[p][3], addr);
            }
#pragma unroll
            for (int mt = 0; mt < 2; mt++)
#pragma unroll
                for (int nt = 0; nt < 8; nt++) {
                    int p = nt >> 1, s = nt & 1;
                    mma16816(d[mt][nt][0], d[mt][nt][1], d[mt][nt][2], d[mt][nt][3],
                             a[mt][0], a[mt][1], a[mt][2], a[mt][3],
                             b[p][2 * s], b[p][2 * s + 1]);
                }
        }
        __syncthreads();
    }

    // epilogue: d[mt][nt]{0,1}=row r, {2,3}=row r+8; cols n,n+1
    const int r = lane >> 2, c2 = (lane & 3) * 2;
#pragma unroll
    for (int mt = 0; mt < 2; mt++) {
#pragma unroll
        for (int nt = 0; nt < 8; nt++) {
            int n = n0 + wn * 64 + nt * 8 + c2;
            size_t m = m0 + wm * 32 + mt * 16 + r;
            float bx = bias[n], by = bias[n + 1];
            float2 o0 = { d[mt][nt][0] + bx, d[mt][nt][1] + by };
            float2 o1 = { d[mt][nt][2] + bx, d[mt][nt][3] + by };
            *(float2*)(C + m * NT + n) = o0;
            *(float2*)(C + (m + 8) * NT + n) = o1;
        }
    }
}

// ---------------- LIF over time (h fp32 -> spikes bf16) ---------------------
template <int MODE>
__global__ void k_lif() {
    const float* h;
    __nv_bfloat16* s;
    int width;
    if (MODE == 1) { h = g_h1; s = g_s1; width = H1n; }
    else           { h = g_h2; s = g_s2; width = H2n; }
    size_t g = (size_t)blockIdx.x * blockDim.x + threadIdx.x;
    if (g >= (size_t)Bn * width) return;
    const size_t step = (size_t)Bn * width;
    size_t idx = g;
    float v = 0.0f;
    const __nv_bfloat16 one = __float2bfloat16(1.0f);
    const __nv_bfloat16 zero = __float2bfloat16(0.0f);
#pragma unroll 4
    for (int t = 0; t < Tn; t++) {
        float hh = h[idx];
        v = v + (hh - v) * 0.5f;
        if (v - 1.0f >= 0.0f) { s[idx] = one; v = 0.0f; }
        else                  { s[idx] = zero; }
        idx += step;
    }
}

// ---------------- output layer: GEMM3 + LIF3 + time-reduce ------------------
__global__ void k_out(const float* __restrict__ Wo, const float* __restrict__ bo,
                      float* __restrict__ out) {
    int warp = (blockIdx.x * blockDim.x + threadIdx.x) >> 5;
    int lane = threadIdx.x & 31;
    if (warp >= Bn) return;
    int b = warp;

    float w[On][8];
#pragma unroll
    for (int k = 0; k < On; k++)
#pragma unroll
        for (int i = 0; i < 8; i++) w[k][i] = Wo[k * H2n + lane + 32 * i];
    float bol[On];
#pragma unroll
    for (int k = 0; k < On; k++) bol[k] = bo[k];

    float vo[On];
    int cnt[On];
#pragma unroll
    for (int k = 0; k < On; k++) { vo[k] = 0.0f; cnt[k] = 0; }

    for (int t = 0; t < Tn; t++) {
        const __nv_bfloat16* s = g_s2 + ((size_t)t * Bn + b) * H2n;
        float sv[8];
#pragma unroll
        for (int i = 0; i < 8; i++) sv[i] = __bfloat162float(s[lane + 32 * i]);
        float acc[On];
#pragma unroll
        for (int k = 0; k < On; k++) acc[k] = 0.0f;
#pragma unroll
        for (int i = 0; i < 8; i++)
#pragma unroll
            for (int k = 0; k < On; k++) acc[k] = fmaf(sv[i], w[k][i], acc[k]);
#pragma unroll
        for (int k = 0; k < On; k++) {
#pragma unroll
            for (int off = 16; off > 0; off >>= 1)
                acc[k] += __shfl_down_sync(0xffffffffu, acc[k], off);
        }
        if (lane == 0) {
#pragma unroll
            for (int k = 0; k < On; k++) {
                float o = acc[k] + bol[k];
                vo[k] = vo[k] + (o - vo[k]) * 0.5f;
                if (vo[k] - 1.0f >= 0.0f) { cnt[k]++; vo[k] = 0.0f; }
            }
        }
    }
    if (lane == 0) {
#pragma unroll
        for (int k = 0; k < On; k++)
            out[(size_t)b * On + k] = (float)cnt[k] / 100.0f;
    }
}

// ---------------------------------------------------------------------------
extern "C" void kernel_launch(void* const* d_in, const int* in_sizes, int n_in,
                              void* d_out, int out_size) {
    const float* x  = (const float*)d_in[0];   // (2048, 512, 100)
    const float* W1 = (const float*)d_in[1];   // (512, 512)
    const float* b1 = (const float*)d_in[2];   // (512)
    const float* W2 = (const float*)d_in[3];   // (256, 512)
    const float* b2 = (const float*)d_in[4];   // (256)
    const float* Wo = (const float*)d_in[5];   // (5, 256)
    const float* bo = (const float*)d_in[6];   // (5)
    float* out = (float*)d_out;                // (2048, 5)

    // 0) 3-way bf16 splits of W1, W2
    k_wsplit<1><<<(H1n * Nin + 255) / 256, 256>>>(W1, H1n * Nin);
    k_wsplit<2><<<(H2n * H1n + 255) / 256, 256>>>(W2, H2n * H1n);
    // 1) transpose + 3-way split x
    k_transpose<<<dim3(Bn, Nin / 32, (Tn + 31) / 32), dim3(32, 8)>>>(x);
    // 2) h1 = x @ W1^T + b1  (bf16x6: fp32-level accuracy on tensor pipe)
    k_gemm<512, 6, 1><<<dim3(H1n / 128, Mn / 128), 256>>>(b1, g_h1);
    // 3) LIF layer 1 -> s1 (bf16 spikes, exact)
    k_lif<1><<<(Bn * H1n) / 256, 256>>>();
    // 4) h2 = s1 @ W2^T + b2  (spikes exact; W2 3-split -> 3 passes)
    k_gemm<256, 3, 2><<<dim3(H2n / 128, Mn / 128), 256>>>(b2, g_h2);
    // 5) LIF layer 2 -> s2
    k_lif<2><<<(Bn * H2n) / 256, 256>>>();
    // 6) output layer GEMM + LIF + spike-count reduce
    k_out<<<Bn / 8, 256>>>(Wo, bo, out);
}

// round 6
// speedup vs baseline: 1.0221x; 1.0221x over previous
#include <cuda_runtime.h>
#include <cuda_fp16.h>
#include <cstdint>

#define Bn   2048
#define Nin  512
#define Tn   100
#define H1n  512
#define H2n  256
#define On   5
#define Mn   (Tn*Bn)   // 204800 rows = (t,b)

// ---------------- scratch (device globals: allocation-free) ----------------
__device__ __half g_xh[(size_t)Mn * Nin];
__device__ __half g_xm[(size_t)Mn * Nin];
__device__ float  g_h1[(size_t)Mn * H1n];
__device__ __half g_s1[(size_t)Mn * H1n];
__device__ float  g_h2[(size_t)Mn * H2n];
__device__ __half g_s2[(size_t)Mn * H2n];
__device__ __half g_W1h[H1n * Nin], g_W1m[H1n * Nin];
__device__ __half g_W2h[H2n * H1n], g_W2m[H2n * H1n];

// ---------------- PTX helpers ----------------------------------------------
__device__ __forceinline__ uint32_t smem_u32(const void* p) {
    uint32_t a;
    asm("{ .reg .u64 t; cvta.to.shared.u64 t, %1; cvt.u32.u64 %0, t; }" : "=r"(a) : "l"(p));
    return a;
}
__device__ __forceinline__ void cp16(uint32_t dst, const void* src) {
    asm volatile("cp.async.cg.shared.global [%0], [%1], 16;" :: "r"(dst), "l"(src));
}
__device__ __forceinline__ void ldsm_x4(uint32_t& r0, uint32_t& r1, uint32_t& r2,
                                        uint32_t& r3, uint32_t addr) {
    asm volatile("ldmatrix.sync.aligned.m8n8.x4.shared.b16 {%0,%1,%2,%3}, [%4];"
                 : "=r"(r0), "=r"(r1), "=r"(r2), "=r"(r3) : "r"(addr));
}
__device__ __forceinline__ void mma16816(float& d0, float& d1, float& d2, float& d3,
                                         uint32_t a0, uint32_t a1, uint32_t a2, uint32_t a3,
                                         uint32_t b0, uint32_t b1) {
    asm volatile("mma.sync.aligned.m16n8k16.row.col.f32.f16.f16.f32 "
                 "{%0,%1,%2,%3}, {%4,%5,%6,%7}, {%8,%9}, {%0,%1,%2,%3};"
                 : "+f"(d0), "+f"(d1), "+f"(d2), "+f"(d3)
                 : "r"(a0), "r"(a1), "r"(a2), "r"(a3), "r"(b0), "r"(b1));
}

// ---------------- weight split: fp32 -> fp16 h/m ----------------------------
template <int MODE>
__global__ void k_wsplit(const float* __restrict__ src, int n) {
    int i = blockIdx.x * blockDim.x + threadIdx.x;
    if (i >= n) return;
    float v = src[i];
    __half h = __float2half_rn(v);
    __half m = __float2half_rn(v - __half2float(h));
    if (MODE == 1) { g_W1h[i] = h; g_W1m[i] = m; }
    else           { g_W2h[i] = h; g_W2m[i] = m; }
}

// ---------------- transpose + 2-split x (B,N,T) -> x{h,m}[(t*B+b)*N + n] ----
__global__ void k_transpose(const float* __restrict__ x) {
    __shared__ float tile[32][33];
    int b  = blockIdx.x;
    int n0 = blockIdx.y * 32;
    int t0 = blockIdx.z * 32;
    int tx = threadIdx.x, ty = threadIdx.y;   // 32 x 8
#pragma unroll
    for (int i = 0; i < 4; i++) {
        int n = n0 + ty + i * 8, t = t0 + tx;
        if (t < Tn) tile[ty + i * 8][tx] = x[((size_t)b * Nin + n) * Tn + t];
    }
    __syncthreads();
#pragma unroll
    for (int i = 0; i < 4; i++) {
        int t = t0 + ty + i * 8, n = n0 + tx;
        if (t < Tn) {
            float v = tile[tx][ty + i * 8];
            __half h = __float2half_rn(v);
            __half m = __float2half_rn(v - __half2float(h));
            size_t idx = ((size_t)t * Bn + b) * Nin + n;
            g_xh[idx] = h; g_xm[idx] = m;
        }
    }
}

// ---------------- HMMA fp16 multi-pass GEMM ---------------------------------
// C[m][n] = sum_pass sum_k Ap[m][k] * Bp[n][k]  + bias[n]
// CTA tile 128x128, BK=32, 8 warps (4M x 2N), warp tile 32x64,
// mma.sync m16n8k16, cp.async double buffer, padded smem (stride 40 fp16).
#define SROW 40   // fp16 elems per smem row (80B: 16B-aligned, conflict-free)

template <int NT, int NPASS, int MODE>
__global__ __launch_bounds__(256) void k_gemm(const float* __restrict__ bias,
                                              float* __restrict__ C) {
    __shared__ __align__(16) __half sA[2][128 * SROW];
    __shared__ __align__(16) __half sB[2][128 * SROW];

    const int tid = threadIdx.x;
    const int wid = tid >> 5;
    const int lane = tid & 31;
    const int wm = wid >> 1;        // 0..3 -> m offset wm*32
    const int wn = wid & 1;         // 0..1 -> n offset wn*64
    const size_t m0 = (size_t)blockIdx.y * 128;
    const int n0 = blockIdx.x * 128;

    const int lrow = tid >> 2;      // 0..63 (load row base, x2)
    const int lch  = tid & 3;       // 16B chunk

    float d[2][8][4];
#pragma unroll
    for (int i = 0; i < 2; i++)
#pragma unroll
        for (int j = 0; j < 8; j++)
#pragma unroll
            for (int k = 0; k < 4; k++) d[i][j][k] = 0.0f;

    const uint32_t sAb = smem_u32(&sA[0][0]);
    const uint32_t sBb = smem_u32(&sB[0][0]);
    const uint32_t bufstride = 128 * SROW * 2;   // bytes per buffer

    auto do_loads = [&](int kc, int buf) {
        int pass = kc >> 4;
        int kb = (kc & 15) * 32;
        const __half *Ap, *Bp;
        if (MODE == 1) {
            // passes: (xh,Wh), (xh,Wm), (xm,Wh)
            Ap = (pass == 2) ? g_xm : g_xh;
            Bp = (pass == 1) ? g_W1m : g_W1h;
        } else {
            Ap = g_s1;
            Bp = (pass == 0) ? g_W2h : g_W2m;
        }
        uint32_t aB = sAb + buf * bufstride;
        uint32_t bB = sBb + buf * bufstride;
#pragma unroll
        for (int i = 0; i < 2; i++) {
            int row = lrow + 64 * i;
            cp16(aB + (row * SROW + lch * 8) * 2, Ap + (m0 + row) * 512 + kb + lch * 8);
            cp16(bB + (row * SROW + lch * 8) * 2, Bp + (size_t)(n0 + row) * 512 + kb + lch * 8);
        }
        asm volatile("cp.async.commit_group;");
    };

    constexpr int KC = NPASS * 16;
    do_loads(0, 0);
    for (int kc = 0; kc < KC; kc++) {
        const int buf = kc & 1;
        if (kc + 1 < KC) {
            do_loads(kc + 1, buf ^ 1);
            asm volatile("cp.async.wait_group 1;");
        } else {
            asm volatile("cp.async.wait_group 0;");
        }
        __syncthreads();

        const uint32_t aB = sAb + buf * bufstride;
        const uint32_t bB = sBb + buf * bufstride;
#pragma unroll
        for (int ks = 0; ks < 2; ks++) {
            // A frags: 2 m16 tiles
            uint32_t a[2][4];
#pragma unroll
            for (int mt = 0; mt < 2; mt++) {
                int row = wm * 32 + mt * 16 + (lane & 15);
                uint32_t addr = aB + (row * SROW + ks * 16) * 2 + (lane >> 4) * 16;
                ldsm_x4(a[mt][0], a[mt][1], a[mt][2], a[mt][3], addr);
            }
            // B frags: 8 n8 tiles, loaded as 4 x4-ldmatrix (2 tiles each)
            uint32_t b[4][4];
#pragma unroll
            for (int p = 0; p < 4; p++) {
                int g = lane >> 3;   // 0..3: (tile 2p + g/2, k-half g&1)
                int row = wn * 64 + (2 * p + (g >> 1)) * 8 + (lane & 7);
                uint32_t addr = bB + (row * SROW + ks * 16) * 2 + (g & 1) * 16;
                ldsm_x4(b[p][0], b[p][1], b[p][2], b[p][3], addr);
            }
#pragma unroll
            for (int mt = 0; mt < 2; mt++)
#pragma unroll
                for (int nt = 0; nt < 8; nt++) {
                    int p = nt >> 1, s = nt & 1;
                    mma16816(d[mt][nt][0], d[mt][nt][1], d[mt][nt][2], d[mt][nt][3],
                             a[mt][0], a[mt][1], a[mt][2], a[mt][3],
                             b[p][2 * s], b[p][2 * s + 1]);
                }
        }
        __syncthreads();
    }

    // epilogue: d[mt][nt]{0,1}=row r, {2,3}=row r+8; cols n,n+1
    const int r = lane >> 2, c2 = (lane & 3) * 2;
#pragma unroll
    for (int mt = 0; mt < 2; mt++) {
#pragma unroll
        for (int nt = 0; nt < 8; nt++) {
            int n = n0 + wn * 64 + nt * 8 + c2;
            size_t m = m0 + wm * 32 + mt * 16 + r;
            float bx = bias[n], by = bias[n + 1];
            float2 o0 = { d[mt][nt][0] + bx, d[mt][nt][1] + by };
            float2 o1 = { d[mt][nt][2] + bx, d[mt][nt][3] + by };
            *(float2*)(C + m * NT + n) = o0;
            *(float2*)(C + (m + 8) * NT + n) = o1;
        }
    }
}

// ---------------- LIF over time (h fp32 -> spikes fp16) ---------------------
template <int MODE>
__global__ void k_lif() {
    const float* h;
    __half* s;
    int width;
    if (MODE == 1) { h = g_h1; s = g_s1; width = H1n; }
    else           { h = g_h2; s = g_s2; width = H2n; }
    size_t g = (size_t)blockIdx.x * blockDim.x + threadIdx.x;
    if (g >= (size_t)Bn * width) return;
    const size_t step = (size_t)Bn * width;
    size_t idx = g;
    float v = 0.0f;
    const __half one = __float2half_rn(1.0f);
    const __half zero = __float2half_rn(0.0f);
#pragma unroll 4
    for (int t = 0; t < Tn; t++) {
        float hh = h[idx];
        v = v + (hh - v) * 0.5f;
        if (v - 1.0f >= 0.0f) { s[idx] = one; v = 0.0f; }
        else                  { s[idx] = zero; }
        idx += step;
    }
}

// ---------------- output layer: GEMM3 + LIF3 + time-reduce ------------------
__global__ void k_out(const float* __restrict__ Wo, const float* __restrict__ bo,
                      float* __restrict__ out) {
    int warp = (blockIdx.x * blockDim.x + threadIdx.x) >> 5;
    int lane = threadIdx.x & 31;
    if (warp >= Bn) return;
    int b = warp;

    float w[On][8];
#pragma unroll
    for (int k = 0; k < On; k++)
#pragma unroll
        for (int i = 0; i < 8; i++) w[k][i] = Wo[k * H2n + lane + 32 * i];
    float bol[On];
#pragma unroll
    for (int k = 0; k < On; k++) bol[k] = bo[k];

    float vo[On];
    int cnt[On];
#pragma unroll
    for (int k = 0; k < On; k++) { vo[k] = 0.0f; cnt[k] = 0; }

    for (int t = 0; t < Tn; t++) {
        const __half* s = g_s2 + ((size_t)t * Bn + b) * H2n;
        float sv[8];
#pragma unroll
        for (int i = 0; i < 8; i++) sv[i] = __half2float(s[lane + 32 * i]);
        float acc[On];
#pragma unroll
        for (int k = 0; k < On; k++) acc[k] = 0.0f;
#pragma unroll
        for (int i = 0; i < 8; i++)
#pragma unroll
            for (int k = 0; k < On; k++) acc[k] = fmaf(sv[i], w[k][i], acc[k]);
#pragma unroll
        for (int k = 0; k < On; k++) {
#pragma unroll
            for (int off = 16; off > 0; off >>= 1)
                acc[k] += __shfl_down_sync(0xffffffffu, acc[k], off);
        }
        if (lane == 0) {
#pragma unroll
            for (int k = 0; k < On; k++) {
                float o = acc[k] + bol[k];
                vo[k] = vo[k] + (o - vo[k]) * 0.5f;
                if (vo[k] - 1.0f >= 0.0f) { cnt[k]++; vo[k] = 0.0f; }
            }
        }
    }
    if (lane == 0) {
#pragma unroll
        for (int k = 0; k < On; k++)
            out[(size_t)b * On + k] = (float)cnt[k] / 100.0f;
    }
}

// ---------------------------------------------------------------------------
extern "C" void kernel_launch(void* const* d_in, const int* in_sizes, int n_in,
                              void* d_out, int out_size) {
    const float* x  = (const float*)d_in[0];   // (2048, 512, 100)
    const float* W1 = (const float*)d_in[1];   // (512, 512)
    const float* b1 = (const float*)d_in[2];   // (512)
    const float* W2 = (const float*)d_in[3];   // (256, 512)
    const float* b2 = (const float*)d_in[4];   // (256)
    const float* Wo = (const float*)d_in[5];   // (5, 256)
    const float* bo = (const float*)d_in[6];   // (5)
    float* out = (float*)d_out;                // (2048, 5)

    // 0) 2-way fp16 splits of W1, W2
    k_wsplit<1><<<(H1n * Nin + 255) / 256, 256>>>(W1, H1n * Nin);
    k_wsplit<2><<<(H2n * H1n + 255) / 256, 256>>>(W2, H2n * H1n);
    // 1) transpose + 2-way fp16 split x
    k_transpose<<<dim3(Bn, Nin / 32, (Tn + 31) / 32), dim3(32, 8)>>>(x);
    // 2) h1 = x @ W1^T + b1  (fp16x3: ~2^-22 accuracy on tensor pipe)
    k_gemm<512, 3, 1><<<dim3(H1n / 128, Mn / 128), 256>>>(b1, g_h1);
    // 3) LIF layer 1 -> s1 (fp16 spikes, exact)
    k_lif<1><<<(Bn * H1n) / 256, 256>>>();
    // 4) h2 = s1 @ W2^T + b2  (spikes exact; W2 2-split -> 2 passes)
    k_gemm<256, 2, 2><<<dim3(H2n / 128, Mn / 128), 256>>>(b2, g_h2);
    // 5) LIF layer 2 -> s2
    k_lif<2><<<(Bn * H2n) / 256, 256>>>();
    // 6) output layer GEMM + LIF + spike-count reduce
    k_out<<<Bn / 8, 256>>>(Wo, bo, out);
}

// round 8
// speedup vs baseline: 1.0241x; 1.0020x over previous
#include <cuda_runtime.h>
#include <cuda_fp16.h>
#include <cstdint>

#define Bn   2048
#define Nin  512
#define Tn   100
#define H1n  512
#define H2n  256
#define On   5
#define Mn   (Tn*Bn)   // 204800 rows = (t,b)

// ---------------- scratch (device globals: allocation-free) ----------------
__device__ __half g_xh[(size_t)Mn * Nin];
__device__ __half g_xm[(size_t)Mn * Nin];
__device__ float  g_h1[(size_t)Mn * H1n];
__device__ __half g_s1[(size_t)Mn * H1n];
__device__ float  g_h2[(size_t)Mn * H2n];
__device__ __half g_s2[(size_t)Mn * H2n];
__device__ __half g_W1h[H1n * Nin], g_W1m[H1n * Nin];
__device__ __half g_W2h[H2n * H1n], g_W2m[H2n * H1n];

// ---------------- PTX helpers ----------------------------------------------
__device__ __forceinline__ uint32_t smem_u32(const void* p) {
    uint32_t a;
    asm("{ .reg .u64 t; cvta.to.shared.u64 t, %1; cvt.u32.u64 %0, t; }" : "=r"(a) : "l"(p));
    return a;
}
__device__ __forceinline__ void cp16(uint32_t dst, const void* src) {
    asm volatile("cp.async.cg.shared.global [%0], [%1], 16;" :: "r"(dst), "l"(src));
}
__device__ __forceinline__ void ldsm_x4(uint32_t& r0, uint32_t& r1, uint32_t& r2,
                                        uint32_t& r3, uint32_t addr) {
    asm volatile("ldmatrix.sync.aligned.m8n8.x4.shared.b16 {%0,%1,%2,%3}, [%4];"
                 : "=r"(r0), "=r"(r1), "=r"(r2), "=r"(r3) : "r"(addr));
}
__device__ __forceinline__ void mma16816(float& d0, float& d1, float& d2, float& d3,
                                         uint32_t a0, uint32_t a1, uint32_t a2, uint32_t a3,
                                         uint32_t b0, uint32_t b1) {
    asm volatile("mma.sync.aligned.m16n8k16.row.col.f32.f16.f16.f32 "
                 "{%0,%1,%2,%3}, {%4,%5,%6,%7}, {%8,%9}, {%0,%1,%2,%3};"
                 : "+f"(d0), "+f"(d1), "+f"(d2), "+f"(d3)
                 : "r"(a0), "r"(a1), "r"(a2), "r"(a3), "r"(b0), "r"(b1));
}

// ---------------- weight split: fp32 -> fp16 h/m ----------------------------
template <int MODE>
__global__ void k_wsplit(const float* __restrict__ src, int n) {
    int i = blockIdx.x * blockDim.x + threadIdx.x;
    if (i >= n) return;
    float v = src[i];
    __half h = __float2half_rn(v);
    __half m = __float2half_rn(v - __half2float(h));
    if (MODE == 1) { g_W1h[i] = h; g_W1m[i] = m; }
    else           { g_W2h[i] = h; g_W2m[i] = m; }
}

// ---------------- transpose + 2-split x (B,N,T) -> x{h,m}[(t*B+b)*N + n] ----
__global__ void k_transpose(const float* __restrict__ x) {
    __shared__ float tile[32][33];
    int b  = blockIdx.x;
    int n0 = blockIdx.y * 32;
    int t0 = blockIdx.z * 32;
    int tx = threadIdx.x, ty = threadIdx.y;   // 32 x 8
#pragma unroll
    for (int i = 0; i < 4; i++) {
        int n = n0 + ty + i * 8, t = t0 + tx;
        if (t < Tn) tile[ty + i * 8][tx] = x[((size_t)b * Nin + n) * Tn + t];
    }
    __syncthreads();
#pragma unroll
    for (int i = 0; i < 4; i++) {
        int t = t0 + ty + i * 8, n = n0 + tx;
        if (t < Tn) {
            float v = tile[tx][ty + i * 8];
            __half h = __float2half_rn(v);
            __half m = __float2half_rn(v - __half2float(h));
            size_t idx = ((size_t)t * Bn + b) * Nin + n;
            g_xh[idx] = h; g_xm[idx] = m;
        }
    }
}

// ---------------- HMMA fp16 multi-pass GEMM ---------------------------------
// CTA tile 128x128, BK=64, 3-stage cp.async ring, 1 sync/iter,
// 8 warps (4M x 2N), warp tile 32x64, mma.sync m16n8k16, XOR-swizzled smem.
// smem row = 64 fp16 = 128B = 8 x 16B chunks; chunk' = chunk ^ (row & 7).
#define STG_BYTES 16384                 // one operand, one stage: 128 rows x 128B
#define SWADDR(base, row, chunk) ((base) + (row) * 128 + (((chunk) ^ ((row) & 7)) << 4))

template <int NT, int NPASS, int MODE>
__global__ __launch_bounds__(256, 2) void k_gemm(const float* __restrict__ bias,
                                                 float* __restrict__ C) {
    extern __shared__ __align__(128) char smem[];
    const uint32_t sb = smem_u32(smem);
    const uint32_t sA = sb;                      // 3 stages A: 48KB
    const uint32_t sB = sb + 3 * STG_BYTES;      // 3 stages B: 48KB

    const int tid = threadIdx.x;
    const int wid = tid >> 5;
    const int lane = tid & 31;
    const int wm = wid >> 1;        // 0..3 -> m offset wm*32
    const int wn = wid & 1;         // 0..1 -> n offset wn*64
    const size_t m0 = (size_t)blockIdx.y * 128;
    const int n0 = blockIdx.x * 128;

    const int lrow = tid >> 1;              // 0..127 load row
    const int lcb  = (tid & 1) * 4;         // chunk base: 0 or 4

    float d[2][8][4];
#pragma unroll
    for (int i = 0; i < 2; i++)
#pragma unroll
        for (int j = 0; j < 8; j++)
#pragma unroll
            for (int k = 0; k < 4; k++) d[i][j][k] = 0.0f;

    auto do_loads = [&](int kc, int slot) {
        int pass = kc >> 3;
        int kb = (kc & 7) * 64;
        const __half *Ap, *Bp;
        if (MODE == 1) {
            // passes: (xh,Wh), (xh,Wm), (xm,Wh)
            Ap = (pass == 2) ? g_xm : g_xh;
            Bp = (pass == 1) ? g_W1m : g_W1h;
        } else {
            Ap = g_s1;
            Bp = (pass == 0) ? g_W2h : g_W2m;
        }
        const uint32_t aB = sA + slot * STG_BYTES;
        const uint32_t bB = sB + slot * STG_BYTES;
        const __half* ag = Ap + (m0 + lrow) * 512 + kb + lcb * 8;
        const __half* bg = Bp + (size_t)(n0 + lrow) * 512 + kb + lcb * 8;
#pragma unroll
        for (int c = 0; c < 4; c++)
            cp16(SWADDR(aB, lrow, lcb + c), ag + c * 8);
#pragma unroll
        for (int c = 0; c < 4; c++)
            cp16(SWADDR(bB, lrow, lcb + c), bg + c * 8);
    };

    constexpr int KC = NPASS * 8;
    do_loads(0, 0);
    asm volatile("cp.async.commit_group;");
    do_loads(1, 1);
    asm volatile("cp.async.commit_group;");

    // ldsm per-lane fixed row indices
    const int arow0 = wm * 32 + (lane & 15);          // + mt*16
    const int achk  = lane >> 4;                      // + ks*2
    const int g     = lane >> 3;
    const int brow0 = wn * 64 + (g >> 1) * 8 + (lane & 7);   // + p*16
    const int bchk  = g & 1;                          // + ks*2

    for (int kc = 0; kc < KC; kc++) {
        asm volatile("cp.async.wait_group 1;");
        __syncthreads();
        const int nk = kc + 2;
        if (nk < KC) do_loads(nk, nk % 3);
        asm volatile("cp.async.commit_group;");

        const int slot = kc % 3;
        const uint32_t aB = sA + slot * STG_BYTES;
        const uint32_t bB = sB + slot * STG_BYTES;
#pragma unroll
        for (int ks = 0; ks < 4; ks++) {
            uint32_t a[2][4];
#pragma unroll
            for (int mt = 0; mt < 2; mt++) {
                int row = arow0 + mt * 16;
                ldsm_x4(a[mt][0], a[mt][1], a[mt][2], a[mt][3],
                        SWADDR(aB, row, ks * 2 + achk));
            }
            uint32_t b[4][4];
#pragma unroll
            for (int p = 0; p < 4; p++) {
                int row = brow0 + p * 16;
                ldsm_x4(b[p][0], b[p][1], b[p][2], b[p][3],
                        SWADDR(bB, row, ks * 2 + bchk));
            }
#pragma unroll
            for (int mt = 0; mt < 2; mt++)
#pragma unroll
                for (int nt = 0; nt < 8; nt++) {
                    int p = nt >> 1, s = nt & 1;
                    mma16816(d[mt][nt][0], d[mt][nt][1], d[mt][nt][2], d[mt][nt][3],
                             a[mt][0], a[mt][1], a[mt][2], a[mt][3],
                             b[p][2 * s], b[p][2 * s + 1]);
                }
        }
    }

    // epilogue: d[mt][nt]{0,1}=row r, {2,3}=row r+8; cols n,n+1
    const int r = lane >> 2, c2 = (lane & 3) * 2;
#pragma unroll
    for (int mt = 0; mt < 2; mt++) {
#pragma unroll
        for (int nt = 0; nt < 8; nt++) {
            int n = n0 + wn * 64 + nt * 8 + c2;
            size_t m = m0 + wm * 32 + mt * 16 + r;
            float bx = bias[n], by = bias[n + 1];
            float2 o0 = { d[mt][nt][0] + bx, d[mt][nt][1] + by };
            float2 o1 = { d[mt][nt][2] + bx, d[mt][nt][3] + by };
            *(float2*)(C + m * NT + n) = o0;
            *(float2*)(C + (m + 8) * NT + n) = o1;
        }
    }
}

// ---------------- LIF over time (h fp32 -> spikes fp16) ---------------------
template <int MODE>
__global__ void k_lif() {
    const float* h;
    __half* s;
    int width;
    if (MODE == 1) { h = g_h1; s = g_s1; width = H1n; }
    else           { h = g_h2; s = g_s2; width = H2n; }
    size_t g = (size_t)blockIdx.x * blockDim.x + threadIdx.x;
    if (g >= (size_t)Bn * width) return;
    const size_t step = (size_t)Bn * width;
    size_t idx = g;
    float v = 0.0f;
    const __half one = __float2half_rn(1.0f);
    const __half zero = __float2half_rn(0.0f);
#pragma unroll 4
    for (int t = 0; t < Tn; t++) {
        float hh = h[idx];
        v = v + (hh - v) * 0.5f;
        if (v - 1.0f >= 0.0f) { s[idx] = one; v = 0.0f; }
        else                  { s[idx] = zero; }
        idx += step;
    }
}

// ---------------- output layer: GEMM3 + LIF3 + time-reduce ------------------
__global__ void k_out(const float* __restrict__ Wo, const float* __restrict__ bo,
                      float* __restrict__ out) {
    int warp = (blockIdx.x * blockDim.x + threadIdx.x) >> 5;
    int lane = threadIdx.x & 31;
    if (warp >= Bn) return;
    int b = warp;

    float w[On][8];
#pragma unroll
    for (int k = 0; k < On; k++)
#pragma unroll
        for (int i = 0; i < 8; i++) w[k][i] = Wo[k * H2n + lane + 32 * i];
    float bol[On];
#pragma unroll
    for (int k = 0; k < On; k++) bol[k] = bo[k];

    float vo[On];
    int cnt[On];
#pragma unroll
    for (int k = 0; k < On; k++) { vo[k] = 0.0f; cnt[k] = 0; }

    for (int t = 0; t < Tn; t++) {
        const __half* s = g_s2 + ((size_t)t * Bn + b) * H2n;
        float sv[8];
#pragma unroll
        for (int i = 0; i < 8; i++) sv[i] = __half2float(s[lane + 32 * i]);
        float acc[On];
#pragma unroll
        for (int k = 0; k < On; k++) acc[k] = 0.0f;
#pragma unroll
        for (int i = 0; i < 8; i++)
#pragma unroll
            for (int k = 0; k < On; k++) acc[k] = fmaf(sv[i], w[k][i], acc[k]);
#pragma unroll
        for (int k = 0; k < On; k++) {
#pragma unroll
            for (int off = 16; off > 0; off >>= 1)
                acc[k] += __shfl_down_sync(0xffffffffu, acc[k], off);
        }
        if (lane == 0) {
#pragma unroll
            for (int k = 0; k < On; k++) {
                float o = acc[k] + bol[k];
                vo[k] = vo[k] + (o - vo[k]) * 0.5f;
                if (vo[k] - 1.0f >= 0.0f) { cnt[k]++; vo[k] = 0.0f; }
            }
        }
    }
    if (lane == 0) {
#pragma unroll
        for (int k = 0; k < On; k++)
            out[(size_t)b * On + k] = (float)cnt[k] / 100.0f;
    }
}

// ---------------------------------------------------------------------------
extern "C" void kernel_launch(void* const* d_in, const int* in_sizes, int n_in,
                              void* d_out, int out_size) {
    const float* x  = (const float*)d_in[0];   // (2048, 512, 100)
    const float* W1 = (const float*)d_in[1];   // (512, 512)
    const float* b1 = (const float*)d_in[2];   // (512)
    const float* W2 = (const float*)d_in[3];   // (256, 512)
    const float* b2 = (const float*)d_in[4];   // (256)
    const float* Wo = (const float*)d_in[5];   // (5, 256)
    const float* bo = (const float*)d_in[6];   // (5)
    float* out = (float*)d_out;                // (2048, 5)

    const int SMEM = 6 * STG_BYTES;            // 96KB dynamic
    static bool attr_done = false;
    if (!attr_done) {
        cudaFuncSetAttribute(k_gemm<512, 3, 1>, cudaFuncAttributeMaxDynamicSharedMemorySize, SMEM);
        cudaFuncSetAttribute(k_gemm<256, 2, 2>, cudaFuncAttributeMaxDynamicSharedMemorySize, SMEM);
        attr_done = true;
    }

    // 0) 2-way fp16 splits of W1, W2
    k_wsplit<1><<<(H1n * Nin + 255) / 256, 256>>>(W1, H1n * Nin);
    k_wsplit<2><<<(H2n * H1n + 255) / 256, 256>>>(W2, H2n * H1n);
    // 1) transpose + 2-way fp16 split x
    k_transpose<<<dim3(Bn, Nin / 32, (Tn + 31) / 32), dim3(32, 8)>>>(x);
    // 2) h1 = x @ W1^T + b1  (fp16x3: ~2^-22 accuracy on tensor pipe)
    k_gemm<512, 3, 1><<<dim3(H1n / 128, Mn / 128), 256, SMEM>>>(b1, g_h1);
    // 3) LIF layer 1 -> s1 (fp16 spikes, exact)
    k_lif<1><<<(Bn * H1n) / 256, 256>>>();
    // 4) h2 = s1 @ W2^T + b2  (spikes exact; W2 2-split -> 2 passes)
    k_gemm<256, 2, 2><<<dim3(H2n / 128, Mn / 128), 256, SMEM>>>(b2, g_h2);
    // 5) LIF layer 2 -> s2
    k_lif<2><<<(Bn * H2n) / 256, 256>>>();
    // 6) output layer GEMM + LIF + spike-count reduce
    k_out<<<Bn / 8, 256>>>(Wo, bo, out);
}